// round 15
// baseline (speedup 1.0000x reference)
#include <cuda_runtime.h>
#include <cuda_fp16.h>
#include <cstdint>

#define Bb   4
#define Ss   4096
#define FIN  512
#define FOUT 512
#define KW   17
#define Gg   8
#define Dd   64
#define PADK 8
#define Mrows (Bb*Ss)   // 16384

__device__ float g_q[(size_t)Mrows*FOUT];
__device__ float g_k[(size_t)Mrows*FOUT];
__device__ __half g_vh[(size_t)Mrows*FOUT];   // v output, fp16 (attn is sole consumer)

// fp16 hi/lo split operands
__device__ __half g_xh[(size_t)Mrows*FIN];
__device__ __half g_xl[(size_t)Mrows*FIN];
__device__ __half g_wh[3][(size_t)FOUT*FIN];
__device__ __half g_wl[3][(size_t)FOUT*FIN];

__device__ unsigned int g_ctr;   // persistent-GEMM tile counter

// ---------------------------------------------------------------------------
__device__ __forceinline__ void mma_f16(float* d, const uint32_t* a,
                                        uint32_t b0, uint32_t b1) {
    asm volatile(
        "mma.sync.aligned.m16n8k16.row.col.f32.f16.f16.f32 "
        "{%0,%1,%2,%3}, {%4,%5,%6,%7}, {%8,%9}, {%0,%1,%2,%3};"
        : "+f"(d[0]), "+f"(d[1]), "+f"(d[2]), "+f"(d[3])
        : "r"(a[0]), "r"(a[1]), "r"(a[2]), "r"(a[3]), "r"(b0), "r"(b1));
}

__device__ __forceinline__ void cp_async16(void* smem, const void* gmem) {
    uint32_t s = (uint32_t)__cvta_generic_to_shared(smem);
    asm volatile("cp.async.cg.shared.global [%0], [%1], 16;" :: "r"(s), "l"(gmem));
}
__device__ __forceinline__ void cp_commit() { asm volatile("cp.async.commit_group;"); }
__device__ __forceinline__ void cp_wait0() { asm volatile("cp.async.wait_group 0;"); }

__device__ __forceinline__ uint64_t pack4h(__half a, __half b, __half c, __half d) {
    return (uint64_t)__half_as_ushort(a)
         | ((uint64_t)__half_as_ushort(b) << 16)
         | ((uint64_t)__half_as_ushort(c) << 32)
         | ((uint64_t)__half_as_ushort(d) << 48);
}

// ---------------------------------------------------------------------------
// Fused pre-pass: one launch splits x AND Wq/Wk/Wv to fp16 hi/lo; resets ctr.
// ---------------------------------------------------------------------------
#define XN4 ((size_t)Mrows * FIN / 4)    // 2097152 float4s
#define WN4 ((size_t)FOUT * FIN / 4)     // 65536 float4s

__global__ __launch_bounds__(256) void split_all(const float* __restrict__ x,
                                                 const float* __restrict__ Wq,
                                                 const float* __restrict__ Wk,
                                                 const float* __restrict__ Wv) {
    const size_t i = (size_t)blockIdx.x * 256 + threadIdx.x;
    if (i == 0) g_ctr = 0u;

    const float* src;
    uint64_t *dh, *dl;
    size_t idx;
    if (i < XN4) {
        src = x; idx = i;
        dh = (uint64_t*)g_xh; dl = (uint64_t*)g_xl;
    } else {
        const size_t j = i - XN4;
        const int z = (int)(j / WN4);
        idx = j % WN4;
        src = (z == 0) ? Wq : (z == 1) ? Wk : Wv;
        dh = (uint64_t*)g_wh[z]; dl = (uint64_t*)g_wl[z];
    }
    float4 v = ((const float4*)src)[idx];
    float a[4] = {v.x, v.y, v.z, v.w};
    __half h[4], l[4];
#pragma unroll
    for (int u = 0; u < 4; u++) {
        h[u] = __float2half_rn(a[u]);
        l[u] = __float2half_rn(a[u] - __half2float(h[u]));
    }
    dh[idx] = pack4h(h[0], h[1], h[2], h[3]);
    dl[idx] = pack4h(l[0], l[1], l[2], l[3]);
}

// ---------------------------------------------------------------------------
// Persistent fp16 GEMM, R15: 128x64 tiles (3072 total) -> finer scheduling
// quantum, tail ~0.6 of a ~20us tile. q (3-pass) tiles dequeue first (LPT).
// Warp tile 32x32 (4 m-warps x 2 n-warps). Arithmetic identical to R14.
// ---------------------------------------------------------------------------
#define NTILES 3072   // 3 z * 128 m-tiles * 8 n-tiles

__global__ __launch_bounds__(256, 2) void gemm_all(void) {
    __shared__ __half Ah[2][2048];   // 128 rows x 16 halves
    __shared__ __half Al[2][2048];
    __shared__ __half Bh[2][1024];   // 64 rows x 16 halves
    __shared__ __half Bl[2][1024];
    __shared__ int s_tile;

    const int tid  = threadIdx.x;

    // A loader: all 256 threads, row = tid>>1, chunk = (tid&1)*8
    const int ra = tid >> 1;
    const int ca = (tid & 1) * 8;
    // B loader: threads 0..127, row = tid>>1, chunk = (tid&1)*8
    const bool bload = (tid < 128);
    const int rb = tid >> 1;          // 0..63 when bload
    const int cb = (tid & 1) * 8;

    const int warp = tid >> 5;
    const int lane = tid & 31;
    const int wm0  = (warp >> 1) * 32;   // 4 warps along M
    const int wn0  = (warp & 1) * 32;    // 2 warps along N (tile N=64)
    const int gid  = lane >> 2;
    const int tig  = lane & 3;

    __half* sah = &Ah[0][ra * 16 + ca];
    __half* sal = &Al[0][ra * 16 + ca];
    __half* sbh = &Bh[0][rb * 16 + cb];
    __half* sbl = &Bl[0][rb * 16 + cb];

    const int NT = FIN / 16;

    while (true) {
        if (tid == 0) s_tile = (int)atomicAdd(&g_ctr, 1u);
        __syncthreads();   // publish s_tile; gates smem reuse across tiles
        const int t0 = s_tile;
        if (t0 >= NTILES) break;

        const int z   = t0 >> 10;         // 1024 tiles per z; z=0 (3-pass) first
        const int rem = t0 & 1023;
        const int m0  = (rem >> 3) * 128;
        const int n0  = (rem & 7) * 64;
        const bool threePass = (z == 0);

        const __half* __restrict__ Wh = g_wh[z];
        const __half* __restrict__ Wl = g_wl[z];

        const __half* agh = g_xh + (size_t)(m0 + ra) * FIN + ca;
        const __half* agl = g_xl + (size_t)(m0 + ra) * FIN + ca;
        const __half* bgh = Wh   + (size_t)(n0 + rb) * FIN + cb;
        const __half* bgl = Wl   + (size_t)(n0 + rb) * FIN + cb;

        float acc[2][4][4];
#pragma unroll
        for (int mt = 0; mt < 2; mt++)
#pragma unroll
            for (int nt = 0; nt < 4; nt++)
#pragma unroll
                for (int i = 0; i < 4; i++) acc[mt][nt][i] = 0.f;

        cp_async16(sah, agh);
        cp_async16(sal, agl);
        if (bload) {
            cp_async16(sbh, bgh);
            if (threePass) cp_async16(sbl, bgl);
        }
        cp_commit();

        for (int t = 0; t < NT; t++) {
            cp_wait0();
            __syncthreads();

            if (t + 1 < NT) {
                const int nb = (t + 1) & 1;
                const int ko = (t + 1) * 16;
                cp_async16(sah + nb * 2048, agh + ko);
                cp_async16(sal + nb * 2048, agl + ko);
                if (bload) {
                    cp_async16(sbh + nb * 1024, bgh + ko);
                    if (threePass) cp_async16(sbl + nb * 1024, bgl + ko);
                }
                cp_commit();
            }

            const __half* Abh = Ah[t & 1];
            const __half* Abl = Al[t & 1];
            const __half* Bbh = Bh[t & 1];
            const __half* Bbl = Bl[t & 1];

            uint32_t a_h[2][4], a_l[2][4];
#pragma unroll
            for (int mt = 0; mt < 2; mt++) {
                const int r0 = wm0 + mt * 16 + gid;
                uint2 v0 = *(const uint2*)&Abh[(r0    ) * 16 + 4 * tig];
                uint2 v1 = *(const uint2*)&Abh[(r0 + 8) * 16 + 4 * tig];
                a_h[mt][0] = v0.x; a_h[mt][1] = v1.x; a_h[mt][2] = v0.y; a_h[mt][3] = v1.y;
                uint2 w0 = *(const uint2*)&Abl[(r0    ) * 16 + 4 * tig];
                uint2 w1 = *(const uint2*)&Abl[(r0 + 8) * 16 + 4 * tig];
                a_l[mt][0] = w0.x; a_l[mt][1] = w1.x; a_l[mt][2] = w0.y; a_l[mt][3] = w1.y;
            }

#pragma unroll
            for (int nt = 0; nt < 4; nt++) {
                const int n = wn0 + nt * 8 + gid;   // 0..63
                uint2 vbh = *(const uint2*)&Bbh[n * 16 + 4 * tig];
#pragma unroll
                for (int mt = 0; mt < 2; mt++) {
                    mma_f16(acc[mt][nt], a_h[mt], vbh.x, vbh.y);  // xh*Wh
                    mma_f16(acc[mt][nt], a_l[mt], vbh.x, vbh.y);  // xl*Wh
                }
                if (threePass) {
                    uint2 vbl = *(const uint2*)&Bbl[n * 16 + 4 * tig];
#pragma unroll
                    for (int mt = 0; mt < 2; mt++)
                        mma_f16(acc[mt][nt], a_h[mt], vbl.x, vbl.y);  // xh*Wl
                }
            }
            // (no bottom barrier — top barrier of next iteration orders reuse)
        }

        if (z < 2) {
            float* __restrict__ C = (z == 0) ? g_q : g_k;
#pragma unroll
            for (int mt = 0; mt < 2; mt++) {
#pragma unroll
                for (int nt = 0; nt < 4; nt++) {
                    const int row = m0 + wm0 + mt * 16 + gid;
                    const int col = n0 + wn0 + nt * 8 + 2 * tig;
                    *(float2*)&C[(size_t)row * FOUT + col] =
                        make_float2(acc[mt][nt][0], acc[mt][nt][1]);
                    *(float2*)&C[(size_t)(row + 8) * FOUT + col] =
                        make_float2(acc[mt][nt][2], acc[mt][nt][3]);
                }
            }
        } else {
#pragma unroll
            for (int mt = 0; mt < 2; mt++) {
#pragma unroll
                for (int nt = 0; nt < 4; nt++) {
                    const int row = m0 + wm0 + mt * 16 + gid;
                    const int col = n0 + wn0 + nt * 8 + 2 * tig;
                    *(__half2*)&g_vh[(size_t)row * FOUT + col] =
                        __floats2half2_rn(acc[mt][nt][0], acc[mt][nt][1]);
                    *(__half2*)&g_vh[(size_t)(row + 8) * FOUT + col] =
                        __floats2half2_rn(acc[mt][nt][2], acc[mt][nt][3]);
                }
            }
        }
    }
}

// ---------------------------------------------------------------------------
// attn (unchanged from R14): k fp32 (stride 68), v fp16 (stride 72 halves).
// ---------------------------------------------------------------------------
#define TSs   64
#define RROWS 80          // TSs + KW - 1
#define KSTR  68
#define VSTR  72

__global__ __launch_bounds__(256, 4) void attn2(
    const float* __restrict__ rel,     // [FOUT, KW]
    float* __restrict__ out,           // [Mrows, FOUT]
    float* __restrict__ attn_out)      // [Mrows, Gg, KW]
{
    __shared__ float  ks[RROWS * KSTR];
    __shared__ __half vs[RROWS * VSTR];
    __shared__ float  rt[KW * Dd];     // relT[j][d]

    const int b   = blockIdx.z;
    const int g   = blockIdx.y;
    const int s0  = blockIdx.x * TSs;
    const int tid = threadIdx.x;
    const int lane = tid & 31, warp = tid >> 5;
    const int sub  = lane >> 3;               // 0..3
    const int sidx = warp * 8 + (lane & 7);   // 0..63
    const int s    = s0 + sidx;
    const int m    = b * Ss + s;

    for (int i = tid; i < RROWS * 16; i += 256) {
        const int r = i >> 4, c = (i & 15) * 4;
        const int gr = s0 - PADK + r;
        float* kd = &ks[r * KSTR + c];
        if (gr >= 0 && gr < Ss) {
            cp_async16(kd, &g_k[((size_t)(b * Ss + gr)) * FOUT + g * Dd + c]);
        } else {
            *(float4*)kd = make_float4(0.f, 0.f, 0.f, 0.f);
        }
    }
    for (int i = tid; i < RROWS * 8; i += 256) {
        const int r = i >> 3, c = (i & 7) * 8;   // c in halves
        const int gr = s0 - PADK + r;
        __half* vd = &vs[r * VSTR + c];
        if (gr >= 0 && gr < Ss) {
            cp_async16(vd, &g_vh[((size_t)(b * Ss + gr)) * FOUT + g * Dd + c]);
        } else {
            *(uint4*)vd = make_uint4(0u, 0u, 0u, 0u);
        }
    }
    {
        const float* rsrc = rel + (size_t)g * Dd * KW;
        for (int i = tid; i < (Dd * KW) / 4; i += 256) {
            float4 v4 = *(const float4*)(rsrc + i * 4);
            float vv[4] = {v4.x, v4.y, v4.z, v4.w};
#pragma unroll
            for (int u = 0; u < 4; u++) {
                const int f = i * 4 + u;
                const int d = f / KW, j = f % KW;
                rt[j * Dd + d] = vv[u];
            }
        }
    }
    cp_commit();
    cp_wait0();
    __syncthreads();

    float4 q4[4];
    {
        const float* qp = &g_q[(size_t)m * FOUT + g * Dd + sub * 16];
#pragma unroll
        for (int c4 = 0; c4 < 4; c4++) q4[c4] = *(const float4*)(qp + 4 * c4);
    }

    float e[KW];
#pragma unroll
    for (int j = 0; j < KW; j++) {
        const float* kr = &ks[(sidx + j) * KSTR + sub * 16];
        const float* rr = &rt[j * Dd + sub * 16];
        float a0 = 0.f, a1 = 0.f;
#pragma unroll
        for (int c4 = 0; c4 < 4; c4++) {
            float4 kv = *(const float4*)(kr + 4 * c4);
            float4 rv = *(const float4*)(rr + 4 * c4);
            a0 = fmaf(q4[c4].x, kv.x + rv.x, a0);
            a1 = fmaf(q4[c4].y, kv.y + rv.y, a1);
            a0 = fmaf(q4[c4].z, kv.z + rv.z, a0);
            a1 = fmaf(q4[c4].w, kv.w + rv.w, a1);
        }
        float acc = a0 + a1;
        acc += __shfl_xor_sync(0xffffffffu, acc, 8);
        acc += __shfl_xor_sync(0xffffffffu, acc, 16);
        e[j] = acc;
    }

    float mx = e[0];
#pragma unroll
    for (int j = 1; j < KW; j++) mx = fmaxf(mx, e[j]);
    float sum = 0.f;
#pragma unroll
    for (int j = 0; j < KW; j++) { e[j] = __expf(e[j] - mx); sum += e[j]; }
    const float inv = 1.f / sum;
#pragma unroll
    for (int j = 0; j < KW; j++) e[j] *= inv;

    {
        float* ap = &attn_out[((size_t)m * Gg + g) * KW];
#pragma unroll
        for (int u = 0; u < 4; u++) {
            const int j = sub * 4 + u;
            float val = (j == 0) ? e[0] : (j == 1) ? e[1] : (j == 2) ? e[2] :
                        (j == 3) ? e[3] : (j == 4) ? e[4] : (j == 5) ? e[5] :
                        (j == 6) ? e[6] : (j == 7) ? e[7] : (j == 8) ? e[8] :
                        (j == 9) ? e[9] : (j == 10) ? e[10] : (j == 11) ? e[11] :
                        (j == 12) ? e[12] : (j == 13) ? e[13] : (j == 14) ? e[14] : e[15];
            ap[j] = val;
        }
        if (sub == 0) ap[16] = e[16];
    }

    float o[16];
#pragma unroll
    for (int u = 0; u < 16; u++) o[u] = 0.f;
#pragma unroll
    for (int j = 0; j < KW; j++) {
        const __half* vr = &vs[(sidx + j) * VSTR + sub * 16];
        uint4 p0 = *(const uint4*)vr;        // halves 0..7
        uint4 p1 = *(const uint4*)(vr + 8);  // halves 8..15
        uint32_t pw[8] = {p0.x, p0.y, p0.z, p0.w, p1.x, p1.y, p1.z, p1.w};
        const float w = e[j];
#pragma unroll
        for (int u = 0; u < 8; u++) {
            float2 f = __half22float2(*(const __half2*)&pw[u]);
            o[2 * u]     = fmaf(w, f.x, o[2 * u]);
            o[2 * u + 1] = fmaf(w, f.y, o[2 * u + 1]);
        }
    }
    {
        float* op = &out[(size_t)m * FOUT + g * Dd + sub * 16];
#pragma unroll
        for (int c4 = 0; c4 < 4; c4++)
            *(float4*)(op + 4 * c4) =
                make_float4(o[4*c4], o[4*c4+1], o[4*c4+2], o[4*c4+3]);
    }
}

// ---------------------------------------------------------------------------
extern "C" void kernel_launch(void* const* d_in, const int* in_sizes, int n_in,
                              void* d_out, int out_size)
{
    const float* x   = (const float*)d_in[0];
    const float* Wq  = (const float*)d_in[1];
    const float* Wk  = (const float*)d_in[2];
    const float* Wv  = (const float*)d_in[3];
    const float* rel = (const float*)d_in[4];

    float* out  = (float*)d_out;
    float* attn = out + (size_t)Mrows * FOUT;

    const int nsplit = (int)((XN4 + 3 * WN4) / 256);
    split_all<<<nsplit, 256>>>(x, Wq, Wk, Wv);

    gemm_all<<<296, 256>>>();

    dim3 ga(Ss / TSs, Gg, Bb);
    attn2<<<ga, 256>>>(rel, out, attn);
}

// round 16
// speedup vs baseline: 1.0363x; 1.0363x over previous
#include <cuda_runtime.h>
#include <cuda_fp16.h>
#include <cstdint>

#define Bb   4
#define Ss   4096
#define FIN  512
#define FOUT 512
#define KW   17
#define Gg   8
#define Dd   64
#define PADK 8
#define Mrows (Bb*Ss)   // 16384

__device__ float g_q[(size_t)Mrows*FOUT];
__device__ float g_k[(size_t)Mrows*FOUT];
__device__ __half g_vh[(size_t)Mrows*FOUT];   // v output, fp16 (attn is sole consumer)

// fp16 hi/lo split operands
__device__ __half g_xh[(size_t)Mrows*FIN];
__device__ __half g_xl[(size_t)Mrows*FIN];
__device__ __half g_wh[3][(size_t)FOUT*FIN];
__device__ __half g_wl[3][(size_t)FOUT*FIN];

__device__ unsigned int g_ctr;   // persistent-GEMM tile counter

// ---------------------------------------------------------------------------
__device__ __forceinline__ void mma_f16(float* d, const uint32_t* a,
                                        uint32_t b0, uint32_t b1) {
    asm volatile(
        "mma.sync.aligned.m16n8k16.row.col.f32.f16.f16.f32 "
        "{%0,%1,%2,%3}, {%4,%5,%6,%7}, {%8,%9}, {%0,%1,%2,%3};"
        : "+f"(d[0]), "+f"(d[1]), "+f"(d[2]), "+f"(d[3])
        : "r"(a[0]), "r"(a[1]), "r"(a[2]), "r"(a[3]), "r"(b0), "r"(b1));
}

__device__ __forceinline__ void cp_async16(void* smem, const void* gmem) {
    uint32_t s = (uint32_t)__cvta_generic_to_shared(smem);
    asm volatile("cp.async.cg.shared.global [%0], [%1], 16;" :: "r"(s), "l"(gmem));
}
__device__ __forceinline__ void cp_commit() { asm volatile("cp.async.commit_group;"); }
__device__ __forceinline__ void cp_wait0() { asm volatile("cp.async.wait_group 0;"); }

__device__ __forceinline__ uint64_t pack4h(__half a, __half b, __half c, __half d) {
    return (uint64_t)__half_as_ushort(a)
         | ((uint64_t)__half_as_ushort(b) << 16)
         | ((uint64_t)__half_as_ushort(c) << 32)
         | ((uint64_t)__half_as_ushort(d) << 48);
}

// ---------------------------------------------------------------------------
// Fused pre-pass: one launch splits x AND Wq/Wk/Wv to fp16 hi/lo; resets ctr.
// ---------------------------------------------------------------------------
#define XN4 ((size_t)Mrows * FIN / 4)    // 2097152 float4s
#define WN4 ((size_t)FOUT * FIN / 4)     // 65536 float4s

__global__ __launch_bounds__(256) void split_all(const float* __restrict__ x,
                                                 const float* __restrict__ Wq,
                                                 const float* __restrict__ Wk,
                                                 const float* __restrict__ Wv) {
    const size_t i = (size_t)blockIdx.x * 256 + threadIdx.x;
    if (i == 0) g_ctr = 0u;

    const float* src;
    uint64_t *dh, *dl;
    size_t idx;
    if (i < XN4) {
        src = x; idx = i;
        dh = (uint64_t*)g_xh; dl = (uint64_t*)g_xl;
    } else {
        const size_t j = i - XN4;
        const int z = (int)(j / WN4);
        idx = j % WN4;
        src = (z == 0) ? Wq : (z == 1) ? Wk : Wv;
        dh = (uint64_t*)g_wh[z]; dl = (uint64_t*)g_wl[z];
    }
    float4 v = ((const float4*)src)[idx];
    float a[4] = {v.x, v.y, v.z, v.w};
    __half h[4], l[4];
#pragma unroll
    for (int u = 0; u < 4; u++) {
        h[u] = __float2half_rn(a[u]);
        l[u] = __float2half_rn(a[u] - __half2float(h[u]));
    }
    dh[idx] = pack4h(h[0], h[1], h[2], h[3]);
    dl[idx] = pack4h(l[0], l[1], l[2], l[3]);
}

// ---------------------------------------------------------------------------
// Persistent fp16 GEMM (R14 shape: 128x128 tiles, 1536 total, LPT order).
// z=0 q: 3 passes (xh*Wh + xl*Wh + xh*Wl)   -> residual ~2^-22
// z=1 k: 2 passes (xh*Wh + xl*Wh)           -> one W-rounding source
// z=2 v: 1 pass  (xh*Wh), fp16 epilogue     -> W + x + store rounding sources
// ---------------------------------------------------------------------------
#define NTILES 1536   // 3 * 128 * 4

__global__ __launch_bounds__(256, 2) void gemm_all(void) {
    __shared__ __half Ah[2][2048];
    __shared__ __half Al[2][2048];
    __shared__ __half Bh[2][2048];
    __shared__ __half Bl[2][2048];
    __shared__ int s_tile;

    const int tid  = threadIdx.x;
    const int lrow = tid >> 1;
    const int lk   = (tid & 1) * 8;

    const int warp = tid >> 5;
    const int lane = tid & 31;
    const int wm0  = (warp >> 1) * 32;
    const int wn0  = (warp & 1) * 64;
    const int gid  = lane >> 2;
    const int tig  = lane & 3;

    __half* sah = &Ah[0][lrow * 16 + lk];
    __half* sal = &Al[0][lrow * 16 + lk];
    __half* sbh = &Bh[0][lrow * 16 + lk];
    __half* sbl = &Bl[0][lrow * 16 + lk];

    const int NT = FIN / 16;

    while (true) {
        if (tid == 0) s_tile = (int)atomicAdd(&g_ctr, 1u);
        __syncthreads();   // publish s_tile; gates smem reuse across tiles
        const int t0 = s_tile;
        if (t0 >= NTILES) break;

        const int z   = t0 >> 9;          // 512 tiles per z; z=0 (3-pass) first
        const int rem = t0 & 511;
        const int m0  = (rem >> 2) * 128;
        const int n0  = (rem & 3) * 128;
        const bool threePass = (z == 0);
        const bool twoPass   = (z < 2);   // xl*Wh pass for q,k only

        const __half* __restrict__ Wh = g_wh[z];
        const __half* __restrict__ Wl = g_wl[z];

        const __half* agh = g_xh + (size_t)(m0 + lrow) * FIN + lk;
        const __half* agl = g_xl + (size_t)(m0 + lrow) * FIN + lk;
        const __half* bgh = Wh   + (size_t)(n0 + lrow) * FIN + lk;
        const __half* bgl = Wl   + (size_t)(n0 + lrow) * FIN + lk;

        float acc[2][8][4];
#pragma unroll
        for (int mt = 0; mt < 2; mt++)
#pragma unroll
            for (int nt = 0; nt < 8; nt++)
#pragma unroll
                for (int i = 0; i < 4; i++) acc[mt][nt][i] = 0.f;

        cp_async16(sah, agh);
        if (twoPass)   cp_async16(sal, agl);
        cp_async16(sbh, bgh);
        if (threePass) cp_async16(sbl, bgl);
        cp_commit();

        for (int t = 0; t < NT; t++) {
            cp_wait0();
            __syncthreads();

            if (t + 1 < NT) {
                const int nb = (t + 1) & 1;
                const int ko = (t + 1) * 16;
                cp_async16(sah + nb * 2048, agh + ko);
                if (twoPass)   cp_async16(sal + nb * 2048, agl + ko);
                cp_async16(sbh + nb * 2048, bgh + ko);
                if (threePass) cp_async16(sbl + nb * 2048, bgl + ko);
                cp_commit();
            }

            const __half* Abh = Ah[t & 1];
            const __half* Abl = Al[t & 1];
            const __half* Bbh = Bh[t & 1];
            const __half* Bbl = Bl[t & 1];

            uint32_t a_h[2][4], a_l[2][4];
#pragma unroll
            for (int mt = 0; mt < 2; mt++) {
                const int r0 = wm0 + mt * 16 + gid;
                uint2 v0 = *(const uint2*)&Abh[(r0    ) * 16 + 4 * tig];
                uint2 v1 = *(const uint2*)&Abh[(r0 + 8) * 16 + 4 * tig];
                a_h[mt][0] = v0.x; a_h[mt][1] = v1.x; a_h[mt][2] = v0.y; a_h[mt][3] = v1.y;
                if (twoPass) {
                    uint2 w0 = *(const uint2*)&Abl[(r0    ) * 16 + 4 * tig];
                    uint2 w1 = *(const uint2*)&Abl[(r0 + 8) * 16 + 4 * tig];
                    a_l[mt][0] = w0.x; a_l[mt][1] = w1.x; a_l[mt][2] = w0.y; a_l[mt][3] = w1.y;
                }
            }

#pragma unroll
            for (int nt = 0; nt < 8; nt++) {
                const int n = wn0 + nt * 8 + gid;
                uint2 vbh = *(const uint2*)&Bbh[n * 16 + 4 * tig];
#pragma unroll
                for (int mt = 0; mt < 2; mt++) {
                    mma_f16(acc[mt][nt], a_h[mt], vbh.x, vbh.y);      // xh*Wh
                    if (twoPass)
                        mma_f16(acc[mt][nt], a_l[mt], vbh.x, vbh.y);  // xl*Wh
                }
                if (threePass) {
                    uint2 vbl = *(const uint2*)&Bbl[n * 16 + 4 * tig];
#pragma unroll
                    for (int mt = 0; mt < 2; mt++)
                        mma_f16(acc[mt][nt], a_h[mt], vbl.x, vbl.y);  // xh*Wl
                }
            }
            // (no bottom barrier — top barrier of next iteration orders reuse)
        }

        if (z < 2) {
            float* __restrict__ C = (z == 0) ? g_q : g_k;
#pragma unroll
            for (int mt = 0; mt < 2; mt++) {
#pragma unroll
                for (int nt = 0; nt < 8; nt++) {
                    const int row = m0 + wm0 + mt * 16 + gid;
                    const int col = n0 + wn0 + nt * 8 + 2 * tig;
                    *(float2*)&C[(size_t)row * FOUT + col] =
                        make_float2(acc[mt][nt][0], acc[mt][nt][1]);
                    *(float2*)&C[(size_t)(row + 8) * FOUT + col] =
                        make_float2(acc[mt][nt][2], acc[mt][nt][3]);
                }
            }
        } else {
#pragma unroll
            for (int mt = 0; mt < 2; mt++) {
#pragma unroll
                for (int nt = 0; nt < 8; nt++) {
                    const int row = m0 + wm0 + mt * 16 + gid;
                    const int col = n0 + wn0 + nt * 8 + 2 * tig;
                    *(__half2*)&g_vh[(size_t)row * FOUT + col] =
                        __floats2half2_rn(acc[mt][nt][0], acc[mt][nt][1]);
                    *(__half2*)&g_vh[(size_t)(row + 8) * FOUT + col] =
                        __floats2half2_rn(acc[mt][nt][2], acc[mt][nt][3]);
                }
            }
        }
    }
}

// ---------------------------------------------------------------------------
// attn (unchanged from R14): k fp32 (stride 68), v fp16 (stride 72 halves).
// ---------------------------------------------------------------------------
#define TSs   64
#define RROWS 80          // TSs + KW - 1
#define KSTR  68
#define VSTR  72

__global__ __launch_bounds__(256, 4) void attn2(
    const float* __restrict__ rel,     // [FOUT, KW]
    float* __restrict__ out,           // [Mrows, FOUT]
    float* __restrict__ attn_out)      // [Mrows, Gg, KW]
{
    __shared__ float  ks[RROWS * KSTR];
    __shared__ __half vs[RROWS * VSTR];
    __shared__ float  rt[KW * Dd];     // relT[j][d]

    const int b   = blockIdx.z;
    const int g   = blockIdx.y;
    const int s0  = blockIdx.x * TSs;
    const int tid = threadIdx.x;
    const int lane = tid & 31, warp = tid >> 5;
    const int sub  = lane >> 3;               // 0..3
    const int sidx = warp * 8 + (lane & 7);   // 0..63
    const int s    = s0 + sidx;
    const int m    = b * Ss + s;

    for (int i = tid; i < RROWS * 16; i += 256) {
        const int r = i >> 4, c = (i & 15) * 4;
        const int gr = s0 - PADK + r;
        float* kd = &ks[r * KSTR + c];
        if (gr >= 0 && gr < Ss) {
            cp_async16(kd, &g_k[((size_t)(b * Ss + gr)) * FOUT + g * Dd + c]);
        } else {
            *(float4*)kd = make_float4(0.f, 0.f, 0.f, 0.f);
        }
    }
    for (int i = tid; i < RROWS * 8; i += 256) {
        const int r = i >> 3, c = (i & 7) * 8;   // c in halves
        const int gr = s0 - PADK + r;
        __half* vd = &vs[r * VSTR + c];
        if (gr >= 0 && gr < Ss) {
            cp_async16(vd, &g_vh[((size_t)(b * Ss + gr)) * FOUT + g * Dd + c]);
        } else {
            *(uint4*)vd = make_uint4(0u, 0u, 0u, 0u);
        }
    }
    {
        const float* rsrc = rel + (size_t)g * Dd * KW;
        for (int i = tid; i < (Dd * KW) / 4; i += 256) {
            float4 v4 = *(const float4*)(rsrc + i * 4);
            float vv[4] = {v4.x, v4.y, v4.z, v4.w};
#pragma unroll
            for (int u = 0; u < 4; u++) {
                const int f = i * 4 + u;
                const int d = f / KW, j = f % KW;
                rt[j * Dd + d] = vv[u];
            }
        }
    }
    cp_commit();
    cp_wait0();
    __syncthreads();

    float4 q4[4];
    {
        const float* qp = &g_q[(size_t)m * FOUT + g * Dd + sub * 16];
#pragma unroll
        for (int c4 = 0; c4 < 4; c4++) q4[c4] = *(const float4*)(qp + 4 * c4);
    }

    float e[KW];
#pragma unroll
    for (int j = 0; j < KW; j++) {
        const float* kr = &ks[(sidx + j) * KSTR + sub * 16];
        const float* rr = &rt[j * Dd + sub * 16];
        float a0 = 0.f, a1 = 0.f;
#pragma unroll
        for (int c4 = 0; c4 < 4; c4++) {
            float4 kv = *(const float4*)(kr + 4 * c4);
            float4 rv = *(const float4*)(rr + 4 * c4);
            a0 = fmaf(q4[c4].x, kv.x + rv.x, a0);
            a1 = fmaf(q4[c4].y, kv.y + rv.y, a1);
            a0 = fmaf(q4[c4].z, kv.z + rv.z, a0);
            a1 = fmaf(q4[c4].w, kv.w + rv.w, a1);
        }
        float acc = a0 + a1;
        acc += __shfl_xor_sync(0xffffffffu, acc, 8);
        acc += __shfl_xor_sync(0xffffffffu, acc, 16);
        e[j] = acc;
    }

    float mx = e[0];
#pragma unroll
    for (int j = 1; j < KW; j++) mx = fmaxf(mx, e[j]);
    float sum = 0.f;
#pragma unroll
    for (int j = 0; j < KW; j++) { e[j] = __expf(e[j] - mx); sum += e[j]; }
    const float inv = 1.f / sum;
#pragma unroll
    for (int j = 0; j < KW; j++) e[j] *= inv;

    {
        float* ap = &attn_out[((size_t)m * Gg + g) * KW];
#pragma unroll
        for (int u = 0; u < 4; u++) {
            const int j = sub * 4 + u;
            float val = (j == 0) ? e[0] : (j == 1) ? e[1] : (j == 2) ? e[2] :
                        (j == 3) ? e[3] : (j == 4) ? e[4] : (j == 5) ? e[5] :
                        (j == 6) ? e[6] : (j == 7) ? e[7] : (j == 8) ? e[8] :
                        (j == 9) ? e[9] : (j == 10) ? e[10] : (j == 11) ? e[11] :
                        (j == 12) ? e[12] : (j == 13) ? e[13] : (j == 14) ? e[14] : e[15];
            ap[j] = val;
        }
        if (sub == 0) ap[16] = e[16];
    }

    float o[16];
#pragma unroll
    for (int u = 0; u < 16; u++) o[u] = 0.f;
#pragma unroll
    for (int j = 0; j < KW; j++) {
        const __half* vr = &vs[(sidx + j) * VSTR + sub * 16];
        uint4 p0 = *(const uint4*)vr;        // halves 0..7
        uint4 p1 = *(const uint4*)(vr + 8);  // halves 8..15
        uint32_t pw[8] = {p0.x, p0.y, p0.z, p0.w, p1.x, p1.y, p1.z, p1.w};
        const float w = e[j];
#pragma unroll
        for (int u = 0; u < 8; u++) {
            float2 f = __half22float2(*(const __half2*)&pw[u]);
            o[2 * u]     = fmaf(w, f.x, o[2 * u]);
            o[2 * u + 1] = fmaf(w, f.y, o[2 * u + 1]);
        }
    }
    {
        float* op = &out[(size_t)m * FOUT + g * Dd + sub * 16];
#pragma unroll
        for (int c4 = 0; c4 < 4; c4++)
            *(float4*)(op + 4 * c4) =
                make_float4(o[4*c4], o[4*c4+1], o[4*c4+2], o[4*c4+3]);
    }
}

// ---------------------------------------------------------------------------
extern "C" void kernel_launch(void* const* d_in, const int* in_sizes, int n_in,
                              void* d_out, int out_size)
{
    const float* x   = (const float*)d_in[0];
    const float* Wq  = (const float*)d_in[1];
    const float* Wk  = (const float*)d_in[2];
    const float* Wv  = (const float*)d_in[3];
    const float* rel = (const float*)d_in[4];

    float* out  = (float*)d_out;
    float* attn = out + (size_t)Mrows * FOUT;

    const int nsplit = (int)((XN4 + 3 * WN4) / 256);
    split_all<<<nsplit, 256>>>(x, Wq, Wk, Wv);

    gemm_all<<<296, 256>>>();

    dim3 ga(Ss / TSs, Gg, Bb);
    attn2<<<ga, 256>>>(rel, out, attn);
}

// round 17
// speedup vs baseline: 1.0541x; 1.0172x over previous
#include <cuda_runtime.h>
#include <cuda_fp16.h>
#include <cstdint>

#define Bb   4
#define Ss   4096
#define FIN  512
#define FOUT 512
#define KW   17
#define Gg   8
#define Dd   64
#define PADK 8
#define Mrows (Bb*Ss)   // 16384

__device__ float  g_q [(size_t)Mrows*FOUT];
__device__ __half g_kh[(size_t)Mrows*FOUT];   // k output, fp16 (attn sole consumer)
__device__ __half g_vh[(size_t)Mrows*FOUT];   // v output, fp16 (attn sole consumer)

// fp16 hi/lo split operands
__device__ __half g_xh[(size_t)Mrows*FIN];
__device__ __half g_xl[(size_t)Mrows*FIN];
__device__ __half g_wh[3][(size_t)FOUT*FIN];
__device__ __half g_wl[3][(size_t)FOUT*FIN];

__device__ unsigned int g_ctr;   // persistent-GEMM tile counter

// ---------------------------------------------------------------------------
__device__ __forceinline__ void mma_f16(float* d, const uint32_t* a,
                                        uint32_t b0, uint32_t b1) {
    asm volatile(
        "mma.sync.aligned.m16n8k16.row.col.f32.f16.f16.f32 "
        "{%0,%1,%2,%3}, {%4,%5,%6,%7}, {%8,%9}, {%0,%1,%2,%3};"
        : "+f"(d[0]), "+f"(d[1]), "+f"(d[2]), "+f"(d[3])
        : "r"(a[0]), "r"(a[1]), "r"(a[2]), "r"(a[3]), "r"(b0), "r"(b1));
}

__device__ __forceinline__ void cp_async16(void* smem, const void* gmem) {
    uint32_t s = (uint32_t)__cvta_generic_to_shared(smem);
    asm volatile("cp.async.cg.shared.global [%0], [%1], 16;" :: "r"(s), "l"(gmem));
}
__device__ __forceinline__ void cp_commit() { asm volatile("cp.async.commit_group;"); }
__device__ __forceinline__ void cp_wait0() { asm volatile("cp.async.wait_group 0;"); }

__device__ __forceinline__ uint64_t pack4h(__half a, __half b, __half c, __half d) {
    return (uint64_t)__half_as_ushort(a)
         | ((uint64_t)__half_as_ushort(b) << 16)
         | ((uint64_t)__half_as_ushort(c) << 32)
         | ((uint64_t)__half_as_ushort(d) << 48);
}

// ---------------------------------------------------------------------------
// Fused pre-pass: split x AND Wq/Wk/Wv to fp16 hi/lo; resets tile counter.
// ---------------------------------------------------------------------------
#define XN4 ((size_t)Mrows * FIN / 4)    // 2097152 float4s
#define WN4 ((size_t)FOUT * FIN / 4)     // 65536 float4s

__global__ __launch_bounds__(256) void split_all(const float* __restrict__ x,
                                                 const float* __restrict__ Wq,
                                                 const float* __restrict__ Wk,
                                                 const float* __restrict__ Wv) {
    const size_t i = (size_t)blockIdx.x * 256 + threadIdx.x;
    if (i == 0) g_ctr = 0u;

    const float* src;
    uint64_t *dh, *dl;
    size_t idx;
    if (i < XN4) {
        src = x; idx = i;
        dh = (uint64_t*)g_xh; dl = (uint64_t*)g_xl;
    } else {
        const size_t j = i - XN4;
        const int z = (int)(j / WN4);
        idx = j % WN4;
        src = (z == 0) ? Wq : (z == 1) ? Wk : Wv;
        dh = (uint64_t*)g_wh[z]; dl = (uint64_t*)g_wl[z];
    }
    float4 v = ((const float4*)src)[idx];
    float a[4] = {v.x, v.y, v.z, v.w};
    __half h[4], l[4];
#pragma unroll
    for (int u = 0; u < 4; u++) {
        h[u] = __float2half_rn(a[u]);
        l[u] = __float2half_rn(a[u] - __half2float(h[u]));
    }
    dh[idx] = pack4h(h[0], h[1], h[2], h[3]);
    dl[idx] = pack4h(l[0], l[1], l[2], l[3]);
}

// ---------------------------------------------------------------------------
// Persistent fp16 GEMM (128x128 tiles, 1536 total, LPT: q 3-pass first).
// z=0 q: 3 passes -> fp32 out; z=1 k: 2 passes -> fp16 out;
// z=2 v: 2 passes -> fp16 out.
// ---------------------------------------------------------------------------
#define NTILES 1536   // 3 * 128 * 4

__global__ __launch_bounds__(256, 2) void gemm_all(void) {
    __shared__ __half Ah[2][2048];
    __shared__ __half Al[2][2048];
    __shared__ __half Bh[2][2048];
    __shared__ __half Bl[2][2048];
    __shared__ int s_tile;

    const int tid  = threadIdx.x;
    const int lrow = tid >> 1;
    const int lk   = (tid & 1) * 8;

    const int warp = tid >> 5;
    const int lane = tid & 31;
    const int wm0  = (warp >> 1) * 32;
    const int wn0  = (warp & 1) * 64;
    const int gid  = lane >> 2;
    const int tig  = lane & 3;

    __half* sah = &Ah[0][lrow * 16 + lk];
    __half* sal = &Al[0][lrow * 16 + lk];
    __half* sbh = &Bh[0][lrow * 16 + lk];
    __half* sbl = &Bl[0][lrow * 16 + lk];

    const int NT = FIN / 16;

    while (true) {
        if (tid == 0) s_tile = (int)atomicAdd(&g_ctr, 1u);
        __syncthreads();   // publish s_tile; gates smem reuse across tiles
        const int t0 = s_tile;
        if (t0 >= NTILES) break;

        const int z   = t0 >> 9;          // 512 tiles per z; z=0 (3-pass) first
        const int rem = t0 & 511;
        const int m0  = (rem >> 2) * 128;
        const int n0  = (rem & 3) * 128;
        const bool threePass = (z == 0);

        const __half* __restrict__ Wh = g_wh[z];
        const __half* __restrict__ Wl = g_wl[z];

        const __half* agh = g_xh + (size_t)(m0 + lrow) * FIN + lk;
        const __half* agl = g_xl + (size_t)(m0 + lrow) * FIN + lk;
        const __half* bgh = Wh   + (size_t)(n0 + lrow) * FIN + lk;
        const __half* bgl = Wl   + (size_t)(n0 + lrow) * FIN + lk;

        float acc[2][8][4];
#pragma unroll
        for (int mt = 0; mt < 2; mt++)
#pragma unroll
            for (int nt = 0; nt < 8; nt++)
#pragma unroll
                for (int i = 0; i < 4; i++) acc[mt][nt][i] = 0.f;

        cp_async16(sah, agh);
        cp_async16(sal, agl);
        cp_async16(sbh, bgh);
        if (threePass) cp_async16(sbl, bgl);
        cp_commit();

        for (int t = 0; t < NT; t++) {
            cp_wait0();
            __syncthreads();

            if (t + 1 < NT) {
                const int nb = (t + 1) & 1;
                const int ko = (t + 1) * 16;
                cp_async16(sah + nb * 2048, agh + ko);
                cp_async16(sal + nb * 2048, agl + ko);
                cp_async16(sbh + nb * 2048, bgh + ko);
                if (threePass) cp_async16(sbl + nb * 2048, bgl + ko);
                cp_commit();
            }

            const __half* Abh = Ah[t & 1];
            const __half* Abl = Al[t & 1];
            const __half* Bbh = Bh[t & 1];
            const __half* Bbl = Bl[t & 1];

            uint32_t a_h[2][4], a_l[2][4];
#pragma unroll
            for (int mt = 0; mt < 2; mt++) {
                const int r0 = wm0 + mt * 16 + gid;
                uint2 v0 = *(const uint2*)&Abh[(r0    ) * 16 + 4 * tig];
                uint2 v1 = *(const uint2*)&Abh[(r0 + 8) * 16 + 4 * tig];
                a_h[mt][0] = v0.x; a_h[mt][1] = v1.x; a_h[mt][2] = v0.y; a_h[mt][3] = v1.y;
                uint2 w0 = *(const uint2*)&Abl[(r0    ) * 16 + 4 * tig];
                uint2 w1 = *(const uint2*)&Abl[(r0 + 8) * 16 + 4 * tig];
                a_l[mt][0] = w0.x; a_l[mt][1] = w1.x; a_l[mt][2] = w0.y; a_l[mt][3] = w1.y;
            }

#pragma unroll
            for (int nt = 0; nt < 8; nt++) {
                const int n = wn0 + nt * 8 + gid;
                uint2 vbh = *(const uint2*)&Bbh[n * 16 + 4 * tig];
#pragma unroll
                for (int mt = 0; mt < 2; mt++) {
                    mma_f16(acc[mt][nt], a_h[mt], vbh.x, vbh.y);  // xh*Wh
                    mma_f16(acc[mt][nt], a_l[mt], vbh.x, vbh.y);  // xl*Wh
                }
                if (threePass) {
                    uint2 vbl = *(const uint2*)&Bbl[n * 16 + 4 * tig];
#pragma unroll
                    for (int mt = 0; mt < 2; mt++)
                        mma_f16(acc[mt][nt], a_h[mt], vbl.x, vbl.y);  // xh*Wl
                }
            }
            // (no bottom barrier — next iteration's top barrier orders reuse)
        }

        if (z == 0) {
#pragma unroll
            for (int mt = 0; mt < 2; mt++) {
#pragma unroll
                for (int nt = 0; nt < 8; nt++) {
                    const int row = m0 + wm0 + mt * 16 + gid;
                    const int col = n0 + wn0 + nt * 8 + 2 * tig;
                    *(float2*)&g_q[(size_t)row * FOUT + col] =
                        make_float2(acc[mt][nt][0], acc[mt][nt][1]);
                    *(float2*)&g_q[(size_t)(row + 8) * FOUT + col] =
                        make_float2(acc[mt][nt][2], acc[mt][nt][3]);
                }
            }
        } else {
            __half* __restrict__ Ch = (z == 1) ? g_kh : g_vh;
#pragma unroll
            for (int mt = 0; mt < 2; mt++) {
#pragma unroll
                for (int nt = 0; nt < 8; nt++) {
                    const int row = m0 + wm0 + mt * 16 + gid;
                    const int col = n0 + wn0 + nt * 8 + 2 * tig;
                    *(__half2*)&Ch[(size_t)row * FOUT + col] =
                        __floats2half2_rn(acc[mt][nt][0], acc[mt][nt][1]);
                    *(__half2*)&Ch[(size_t)(row + 8) * FOUT + col] =
                        __floats2half2_rn(acc[mt][nt][2], acc[mt][nt][3]);
                }
            }
        }
    }
}

// ---------------------------------------------------------------------------
// attn: k AND v fp16 in smem (stride 72 halves = 144B rows, conflict-free);
// q and rel fp32; all arithmetic fp32.
// ---------------------------------------------------------------------------
#define TSs   64
#define RROWS 80          // TSs + KW - 1
#define HSTR  72

__global__ __launch_bounds__(256, 4) void attn2(
    const float* __restrict__ rel,     // [FOUT, KW]
    float* __restrict__ out,           // [Mrows, FOUT]
    float* __restrict__ attn_out)      // [Mrows, Gg, KW]
{
    __shared__ __half ks[RROWS * HSTR];
    __shared__ __half vs[RROWS * HSTR];
    __shared__ float  rt[KW * Dd];     // relT[j][d]

    const int b   = blockIdx.z;
    const int g   = blockIdx.y;
    const int s0  = blockIdx.x * TSs;
    const int tid = threadIdx.x;
    const int lane = tid & 31, warp = tid >> 5;
    const int sub  = lane >> 3;               // 0..3
    const int sidx = warp * 8 + (lane & 7);   // 0..63
    const int s    = s0 + sidx;
    const int m    = b * Ss + s;

    // k+v tiles: fp16, 8 x 16B chunks per row each
    for (int i = tid; i < RROWS * 8; i += 256) {
        const int r = i >> 3, c = (i & 7) * 8;   // c in halves
        const int gr = s0 - PADK + r;
        __half* kd = &ks[r * HSTR + c];
        __half* vd = &vs[r * HSTR + c];
        if (gr >= 0 && gr < Ss) {
            const size_t gbase = ((size_t)(b * Ss + gr)) * FOUT + g * Dd + c;
            cp_async16(kd, &g_kh[gbase]);
            cp_async16(vd, &g_vh[gbase]);
        } else {
            *(uint4*)kd = make_uint4(0u, 0u, 0u, 0u);
            *(uint4*)vd = make_uint4(0u, 0u, 0u, 0u);
        }
    }
    {
        const float* rsrc = rel + (size_t)g * Dd * KW;
        for (int i = tid; i < (Dd * KW) / 4; i += 256) {
            float4 v4 = *(const float4*)(rsrc + i * 4);
            float vv[4] = {v4.x, v4.y, v4.z, v4.w};
#pragma unroll
            for (int u = 0; u < 4; u++) {
                const int f = i * 4 + u;
                const int d = f / KW, j = f % KW;
                rt[j * Dd + d] = vv[u];
            }
        }
    }
    cp_commit();
    cp_wait0();
    __syncthreads();

    float4 q4[4];
    {
        const float* qp = &g_q[(size_t)m * FOUT + g * Dd + sub * 16];
#pragma unroll
        for (int c4 = 0; c4 < 4; c4++) q4[c4] = *(const float4*)(qp + 4 * c4);
    }

    float e[KW];
#pragma unroll
    for (int j = 0; j < KW; j++) {
        const __half* kr = &ks[(sidx + j) * HSTR + sub * 16];
        const float*  rr = &rt[j * Dd + sub * 16];
        uint4 kp0 = *(const uint4*)kr;        // halves 0..7
        uint4 kp1 = *(const uint4*)(kr + 8);  // halves 8..15
        uint32_t kw[8] = {kp0.x, kp0.y, kp0.z, kp0.w, kp1.x, kp1.y, kp1.z, kp1.w};
        float a0 = 0.f, a1 = 0.f;
#pragma unroll
        for (int c4 = 0; c4 < 4; c4++) {
            float2 ka = __half22float2(*(const __half2*)&kw[2 * c4]);
            float2 kb = __half22float2(*(const __half2*)&kw[2 * c4 + 1]);
            float4 rv = *(const float4*)(rr + 4 * c4);
            a0 = fmaf(q4[c4].x, ka.x + rv.x, a0);
            a1 = fmaf(q4[c4].y, ka.y + rv.y, a1);
            a0 = fmaf(q4[c4].z, kb.x + rv.z, a0);
            a1 = fmaf(q4[c4].w, kb.y + rv.w, a1);
        }
        float acc = a0 + a1;
        acc += __shfl_xor_sync(0xffffffffu, acc, 8);
        acc += __shfl_xor_sync(0xffffffffu, acc, 16);
        e[j] = acc;
    }

    float mx = e[0];
#pragma unroll
    for (int j = 1; j < KW; j++) mx = fmaxf(mx, e[j]);
    float sum = 0.f;
#pragma unroll
    for (int j = 0; j < KW; j++) { e[j] = __expf(e[j] - mx); sum += e[j]; }
    const float inv = 1.f / sum;
#pragma unroll
    for (int j = 0; j < KW; j++) e[j] *= inv;

    {
        float* ap = &attn_out[((size_t)m * Gg + g) * KW];
#pragma unroll
        for (int u = 0; u < 4; u++) {
            const int j = sub * 4 + u;
            float val = (j == 0) ? e[0] : (j == 1) ? e[1] : (j == 2) ? e[2] :
                        (j == 3) ? e[3] : (j == 4) ? e[4] : (j == 5) ? e[5] :
                        (j == 6) ? e[6] : (j == 7) ? e[7] : (j == 8) ? e[8] :
                        (j == 9) ? e[9] : (j == 10) ? e[10] : (j == 11) ? e[11] :
                        (j == 12) ? e[12] : (j == 13) ? e[13] : (j == 14) ? e[14] : e[15];
            ap[j] = val;
        }
        if (sub == 0) ap[16] = e[16];
    }

    float o[16];
#pragma unroll
    for (int u = 0; u < 16; u++) o[u] = 0.f;
#pragma unroll
    for (int j = 0; j < KW; j++) {
        const __half* vr = &vs[(sidx + j) * HSTR + sub * 16];
        uint4 p0 = *(const uint4*)vr;
        uint4 p1 = *(const uint4*)(vr + 8);
        uint32_t pw[8] = {p0.x, p0.y, p0.z, p0.w, p1.x, p1.y, p1.z, p1.w};
        const float w = e[j];
#pragma unroll
        for (int u = 0; u < 8; u++) {
            float2 f = __half22float2(*(const __half2*)&pw[u]);
            o[2 * u]     = fmaf(w, f.x, o[2 * u]);
            o[2 * u + 1] = fmaf(w, f.y, o[2 * u + 1]);
        }
    }
    {
        float* op = &out[(size_t)m * FOUT + g * Dd + sub * 16];
#pragma unroll
        for (int c4 = 0; c4 < 4; c4++)
            *(float4*)(op + 4 * c4) =
                make_float4(o[4*c4], o[4*c4+1], o[4*c4+2], o[4*c4+3]);
    }
}

// ---------------------------------------------------------------------------
extern "C" void kernel_launch(void* const* d_in, const int* in_sizes, int n_in,
                              void* d_out, int out_size)
{
    const float* x   = (const float*)d_in[0];
    const float* Wq  = (const float*)d_in[1];
    const float* Wk  = (const float*)d_in[2];
    const float* Wv  = (const float*)d_in[3];
    const float* rel = (const float*)d_in[4];

    float* out  = (float*)d_out;
    float* attn = out + (size_t)Mrows * FOUT;

    const int nsplit = (int)((XN4 + 3 * WN4) / 256);
    split_all<<<nsplit, 256>>>(x, Wq, Wk, Wv);

    gemm_all<<<296, 256>>>();

    dim3 ga(Ss / TSs, Gg, Bb);
    attn2<<<ga, 256>>>(rel, out, attn);
}